// round 4
// baseline (speedup 1.0000x reference)
#include <cuda_runtime.h>

#define N_NODES 100000
#define N_EDGES 1600000
#define HID 128
#define C_OUT 64
#define NB_SCAN 98  // ceil(100000/1024)

// ---- scratch (__device__ globals; allocation-free rule) ----
__device__ __align__(16) float g_dis[N_NODES];
__device__ int   g_cnt[N_NODES];
__device__ int   g_cursor[N_NODES];
__device__ int   g_incl[N_NODES];
__device__ int   g_part[128];
__device__ int   g_partx[128];
__device__ int   g_row_start[N_NODES + 1];
__device__ int   g_csr_src[N_EDGES];
__device__ __align__(16) float g_csr_w[N_EDGES];
__device__ __align__(16) float g_g0[(size_t)N_NODES * HID];  // x @ W1
__device__ __align__(16) float g_h [(size_t)N_NODES * HID];  // Agg(g0) + b1
__device__ __align__(16) float g_ah[(size_t)N_NODES * HID];  // Agg(h)

// ---------------- degree / CSR build ----------------
__global__ void k_zero_cnt() {
    int i = blockIdx.x * blockDim.x + threadIdx.x;
    if (i < N_NODES) g_cnt[i] = 0;
}

__global__ void k_hist(const int* __restrict__ ei) {
    int e = blockIdx.x * blockDim.x + threadIdx.x;
    if (e < N_EDGES) {
        unsigned d = (unsigned)ei[N_EDGES + e];
        if (d < N_NODES) atomicAdd(&g_cnt[d], 1);
    }
}

__global__ void k_dis() {
    int i = blockIdx.x * blockDim.x + threadIdx.x;
    if (i < N_NODES) g_dis[i] = rsqrtf((float)g_cnt[i] + 1.0f);
}

__global__ void k_scan1() {
    __shared__ int sm[1024];
    int i = blockIdx.x * 1024 + threadIdx.x;
    sm[threadIdx.x] = (i < N_NODES) ? g_cnt[i] : 0;
    __syncthreads();
#pragma unroll
    for (int off = 1; off < 1024; off <<= 1) {
        int t = (threadIdx.x >= off) ? sm[threadIdx.x - off] : 0;
        __syncthreads();
        sm[threadIdx.x] += t;
        __syncthreads();
    }
    if (i < N_NODES) g_incl[i] = sm[threadIdx.x];
    if (threadIdx.x == 1023) g_part[blockIdx.x] = sm[1023];
}

__global__ void k_scan2() {
    __shared__ int sm[128];
    int t = threadIdx.x;
    int v = (t < NB_SCAN) ? g_part[t] : 0;
    sm[t] = v;
    __syncthreads();
#pragma unroll
    for (int off = 1; off < 128; off <<= 1) {
        int u = (t >= off) ? sm[t - off] : 0;
        __syncthreads();
        sm[t] += u;
        __syncthreads();
    }
    g_partx[t] = sm[t] - v;  // exclusive
}

__global__ void k_scan3() {
    int i = blockIdx.x * blockDim.x + threadIdx.x;
    if (i < N_NODES) {
        int rs = g_incl[i] - g_cnt[i] + g_partx[i >> 10];
        g_row_start[i] = rs;
        g_cursor[i] = rs;
    }
    if (i == 0) g_row_start[N_NODES] = N_EDGES;
}

__global__ void k_fill(const int* __restrict__ ei) {
    int e = blockIdx.x * blockDim.x + threadIdx.x;
    if (e < N_EDGES) {
        unsigned s = (unsigned)ei[e];
        unsigned d = (unsigned)ei[N_EDGES + e];
        if (s < N_NODES && d < N_NODES) {
            int pos = atomicAdd(&g_cursor[d], 1);
            g_csr_src[pos] = s;
            g_csr_w[pos] = g_dis[s];
        }
    }
}

// ---------------- GEMM1: g0 = X @ W1 ----------------
// 64 rows/block, 256 threads; thread = 8 rows x 4 cols. K = 128.
__global__ void __launch_bounds__(256) k_gemm1(const float* __restrict__ X,
                                               const float* __restrict__ W) {
    __shared__ float xsT[128][64];
    const int tid = threadIdx.x;
    const int row0 = blockIdx.x * 64;

    {   // load + transpose X tile [64x128] into xsT[k][r] with segment swizzle
        int row = tid >> 2, seg = tid & 3;
        int gr = row0 + row;
        int rs = row ^ (seg << 3);
        if (gr < N_NODES) {
            const float4* xr = (const float4*)(X + (size_t)gr * 128 + seg * 32);
#pragma unroll
            for (int i = 0; i < 8; i++) {
                float4 v = xr[i];
                int c = seg * 32 + i * 4;
                xsT[c + 0][rs] = v.x; xsT[c + 1][rs] = v.y;
                xsT[c + 2][rs] = v.z; xsT[c + 3][rs] = v.w;
            }
        } else {
#pragma unroll
            for (int i = 0; i < 8; i++) {
                int c = seg * 32 + i * 4;
                xsT[c + 0][rs] = 0.f; xsT[c + 1][rs] = 0.f;
                xsT[c + 2][rs] = 0.f; xsT[c + 3][rs] = 0.f;
            }
        }
    }
    __syncthreads();

    const int ty = tid >> 5, lane = tid & 31, col = lane * 4;
    float acc[8][4];
#pragma unroll
    for (int i = 0; i < 8; i++)
#pragma unroll
        for (int j = 0; j < 4; j++) acc[i][j] = 0.f;

    for (int q = 0; q < 4; q++) {
        const int rb = ((ty ^ q) & 7) * 8;
#pragma unroll
        for (int kk = 0; kk < 32; kk++) {
            const int k = q * 32 + kk;
            float4 xa = *(const float4*)&xsT[k][rb];
            float4 xb = *(const float4*)&xsT[k][rb + 4];
            float4 wv = *(const float4*)(W + (size_t)k * 128 + col);
            float xr[8] = {xa.x, xa.y, xa.z, xa.w, xb.x, xb.y, xb.z, xb.w};
#pragma unroll
            for (int i = 0; i < 8; i++) {
                acc[i][0] += xr[i] * wv.x;
                acc[i][1] += xr[i] * wv.y;
                acc[i][2] += xr[i] * wv.z;
                acc[i][3] += xr[i] * wv.w;
            }
        }
    }

#pragma unroll
    for (int i = 0; i < 8; i++) {
        int r = row0 + ty * 8 + i;
        if (r < N_NODES)
            *(float4*)(g_g0 + (size_t)r * 128 + col) =
                make_float4(acc[i][0], acc[i][1], acc[i][2], acc[i][3]);
    }
}

// ---------------- gather aggregation (one warp per dst node) ----------------
// PASS 0: h[d]  = b1 + dis_d * (dis_d*g0[d] + sum_j dis[s_j]*g0[s_j])
// PASS 1: ah[d] =      dis_d * (dis_d*h[d]  + sum_j dis[s_j]*h[s_j])
template <int PASS>
__global__ void __launch_bounds__(256) k_gather(const float* __restrict__ b1) {
    int w = (blockIdx.x * 256 + threadIdx.x) >> 5;
    if (w >= N_NODES) return;
    int lane = threadIdx.x & 31;
    const float* __restrict__ fin = (PASS == 0) ? g_g0 : g_h;
    float* __restrict__ fout = (PASS == 0) ? g_h : g_ah;

    int start = g_row_start[w];
    int end   = g_row_start[w + 1];
    float disd = g_dis[w];

    float4 self = ((const float4*)(fin + (size_t)w * 128))[lane];
    float4 acc = make_float4(self.x * disd, self.y * disd,
                             self.z * disd, self.w * disd);

    int j = start;
    for (; j + 4 <= end; j += 4) {
        int s0 = g_csr_src[j + 0], s1 = g_csr_src[j + 1];
        int s2 = g_csr_src[j + 2], s3 = g_csr_src[j + 3];
        float w0 = g_csr_w[j + 0], w1 = g_csr_w[j + 1];
        float w2 = g_csr_w[j + 2], w3 = g_csr_w[j + 3];
        float4 v0 = ((const float4*)(fin + (size_t)s0 * 128))[lane];
        float4 v1 = ((const float4*)(fin + (size_t)s1 * 128))[lane];
        float4 v2 = ((const float4*)(fin + (size_t)s2 * 128))[lane];
        float4 v3 = ((const float4*)(fin + (size_t)s3 * 128))[lane];
        acc.x += v0.x * w0; acc.y += v0.y * w0; acc.z += v0.z * w0; acc.w += v0.w * w0;
        acc.x += v1.x * w1; acc.y += v1.y * w1; acc.z += v1.z * w1; acc.w += v1.w * w1;
        acc.x += v2.x * w2; acc.y += v2.y * w2; acc.z += v2.z * w2; acc.w += v2.w * w2;
        acc.x += v3.x * w3; acc.y += v3.y * w3; acc.z += v3.z * w3; acc.w += v3.w * w3;
    }
    for (; j < end; j++) {
        int s = g_csr_src[j];
        float ws = g_csr_w[j];
        float4 v = ((const float4*)(fin + (size_t)s * 128))[lane];
        acc.x += v.x * ws; acc.y += v.y * ws; acc.z += v.z * ws; acc.w += v.w * ws;
    }

    acc.x *= disd; acc.y *= disd; acc.z *= disd; acc.w *= disd;
    if (PASS == 0) {
        float4 bv = ((const float4*)b1)[lane];
        acc.x += bv.x; acc.y += bv.y; acc.z += bv.z; acc.w += bv.w;
    }
    ((float4*)(fout + (size_t)w * 128))[lane] = acc;
}

// ---------------- GEMM2 + epilogue ----------------
// mu = ah@Wmu + bmu ; ls = ah@Wls + bls ; z = mu + eps*exp(ls)
__global__ void __launch_bounds__(256) k_gemm2(const float* __restrict__ Wmu,
                                               const float* __restrict__ bmu,
                                               const float* __restrict__ Wls,
                                               const float* __restrict__ bls,
                                               const float* __restrict__ eps,
                                               float* __restrict__ out) {
    __shared__ float xsT[128][64];
    const int tid = threadIdx.x;
    const int row0 = blockIdx.x * 64;

    {
        int row = tid >> 2, seg = tid & 3;
        int gr = row0 + row;
        int rs = row ^ (seg << 3);
        if (gr < N_NODES) {
            const float4* xr = (const float4*)(g_ah + (size_t)gr * 128 + seg * 32);
#pragma unroll
            for (int i = 0; i < 8; i++) {
                float4 v = xr[i];
                int c = seg * 32 + i * 4;
                xsT[c + 0][rs] = v.x; xsT[c + 1][rs] = v.y;
                xsT[c + 2][rs] = v.z; xsT[c + 3][rs] = v.w;
            }
        } else {
#pragma unroll
            for (int i = 0; i < 8; i++) {
                int c = seg * 32 + i * 4;
                xsT[c + 0][rs] = 0.f; xsT[c + 1][rs] = 0.f;
                xsT[c + 2][rs] = 0.f; xsT[c + 3][rs] = 0.f;
            }
        }
    }
    __syncthreads();

    const int ty = tid >> 5, lane = tid & 31;
    const int jc = lane * 2;  // 2 cols per thread of each of mu/ls

    float am[8][2], al[8][2];
#pragma unroll
    for (int i = 0; i < 8; i++) {
        am[i][0] = am[i][1] = 0.f;
        al[i][0] = al[i][1] = 0.f;
    }

    for (int q = 0; q < 4; q++) {
        const int rb = ((ty ^ q) & 7) * 8;
#pragma unroll
        for (int kk = 0; kk < 32; kk++) {
            const int k = q * 32 + kk;
            float4 xa = *(const float4*)&xsT[k][rb];
            float4 xb = *(const float4*)&xsT[k][rb + 4];
            float2 wm = *(const float2*)(Wmu + (size_t)k * 64 + jc);
            float2 wl = *(const float2*)(Wls + (size_t)k * 64 + jc);
            float xr[8] = {xa.x, xa.y, xa.z, xa.w, xb.x, xb.y, xb.z, xb.w};
#pragma unroll
            for (int i = 0; i < 8; i++) {
                am[i][0] += xr[i] * wm.x;
                am[i][1] += xr[i] * wm.y;
                al[i][0] += xr[i] * wl.x;
                al[i][1] += xr[i] * wl.y;
            }
        }
    }

    const size_t NOUT = (size_t)N_NODES * C_OUT;
    float bm0 = bmu[jc], bm1 = bmu[jc + 1];
    float bl0 = bls[jc], bl1 = bls[jc + 1];
#pragma unroll
    for (int i = 0; i < 8; i++) {
        int r = row0 + ty * 8 + i;
        if (r >= N_NODES) continue;
        float mu0 = am[i][0] + bm0;
        float mu1 = am[i][1] + bm1;
        float ls0 = al[i][0] + bl0;
        float ls1 = al[i][1] + bl1;
        float2 ev = *(const float2*)(eps + (size_t)r * 64 + jc);
        float z0 = mu0 + ev.x * __expf(ls0);
        float z1 = mu1 + ev.y * __expf(ls1);
        size_t off = (size_t)r * 64 + jc;
        *(float2*)(out + off)            = make_float2(z0, z1);
        *(float2*)(out + NOUT + off)     = make_float2(mu0, mu1);
        *(float2*)(out + 2 * NOUT + off) = make_float2(ls0, ls1);
    }
}

extern "C" void kernel_launch(void* const* d_in, const int* in_sizes, int n_in,
                              void* d_out, int out_size) {
    const float* x   = (const float*)d_in[0];
    const int*   ei  = (const int*)d_in[1];   // int32! JAX demotes int64 silently
    const float* W1  = (const float*)d_in[2];
    const float* b1  = (const float*)d_in[3];
    const float* Wmu = (const float*)d_in[4];
    const float* bmu = (const float*)d_in[5];
    const float* Wls = (const float*)d_in[6];
    const float* bls = (const float*)d_in[7];
    const float* eps = (const float*)d_in[8];
    float* out       = (float*)d_out;
    (void)in_sizes; (void)n_in; (void)out_size;

    // degree + CSR build
    k_zero_cnt<<<(N_NODES + 255) / 256, 256>>>();
    k_hist<<<(N_EDGES + 255) / 256, 256>>>(ei);
    k_dis<<<(N_NODES + 255) / 256, 256>>>();
    k_scan1<<<NB_SCAN, 1024>>>();
    k_scan2<<<1, 128>>>();
    k_scan3<<<(N_NODES + 255) / 256, 256>>>();
    k_fill<<<(N_EDGES + 255) / 256, 256>>>(ei);

    // g0 = x @ W1
    k_gemm1<<<(N_NODES + 63) / 64, 256>>>(x, W1);
    // h = Agg(g0) + b1
    k_gather<0><<<(N_NODES + 7) / 8, 256>>>(b1);
    // ah = Agg(h)
    k_gather<1><<<(N_NODES + 7) / 8, 256>>>(b1);
    // mu/logstd/z
    k_gemm2<<<(N_NODES + 63) / 64, 256>>>(Wmu, bmu, Wls, bls, eps, out);
}

// round 5
// speedup vs baseline: 1.1723x; 1.1723x over previous
#include <cuda_runtime.h>
#include <cuda_fp16.h>

#define N_NODES 100000
#define N_EDGES 1600000
#define HID 128
#define C_OUT 64
#define NB_SCAN 98  // ceil(100000/1024)

// ---- scratch (__device__ globals; allocation-free rule) ----
__device__ __align__(16) float g_dis[N_NODES];
__device__ int   g_cnt[N_NODES];
__device__ int   g_cursor[N_NODES];
__device__ int   g_incl[N_NODES];
__device__ int   g_part[128];
__device__ int   g_partx[128];
__device__ int   g_row_start[N_NODES + 1];
__device__ int   g_csr_src[N_EDGES];
__device__ __align__(16) float  g_csr_w[N_EDGES];
__device__ __align__(16) __half g_g0h[(size_t)N_NODES * HID];  // x @ W1   (fp16)
__device__ __align__(16) __half g_hh [(size_t)N_NODES * HID];  // h        (fp16)
__device__ __align__(16) float  g_ah [(size_t)N_NODES * HID];  // Agg(h)   (fp32)

// ---------- f32x2 helpers ----------
#define FMA2(d, a, b) asm("fma.rn.f32x2 %0, %1, %2, %0;" : "+l"(d) : "l"(a), "l"(b))
#define PACK_BB(d, f) asm("mov.b64 %0, {%1, %1};" : "=l"(d) : "f"(f))
#define UNPACK2(lo, hi, d) asm("mov.b64 {%0, %1}, %2;" : "=f"(lo), "=f"(hi) : "l"(d))

// ---------------- degree / CSR build ----------------
__global__ void k_zero_cnt() {
    int i = blockIdx.x * blockDim.x + threadIdx.x;
    if (i < N_NODES) g_cnt[i] = 0;
}

__global__ void k_hist(const int* __restrict__ ei) {
    int e = blockIdx.x * blockDim.x + threadIdx.x;
    if (e < N_EDGES) {
        unsigned d = (unsigned)ei[N_EDGES + e];
        if (d < N_NODES) atomicAdd(&g_cnt[d], 1);
    }
}

__global__ void k_dis() {
    int i = blockIdx.x * blockDim.x + threadIdx.x;
    if (i < N_NODES) g_dis[i] = rsqrtf((float)g_cnt[i] + 1.0f);
}

__global__ void k_scan1() {
    __shared__ int sm[1024];
    int i = blockIdx.x * 1024 + threadIdx.x;
    sm[threadIdx.x] = (i < N_NODES) ? g_cnt[i] : 0;
    __syncthreads();
#pragma unroll
    for (int off = 1; off < 1024; off <<= 1) {
        int t = (threadIdx.x >= off) ? sm[threadIdx.x - off] : 0;
        __syncthreads();
        sm[threadIdx.x] += t;
        __syncthreads();
    }
    if (i < N_NODES) g_incl[i] = sm[threadIdx.x];
    if (threadIdx.x == 1023) g_part[blockIdx.x] = sm[1023];
}

__global__ void k_scan2() {
    __shared__ int sm[128];
    int t = threadIdx.x;
    int v = (t < NB_SCAN) ? g_part[t] : 0;
    sm[t] = v;
    __syncthreads();
#pragma unroll
    for (int off = 1; off < 128; off <<= 1) {
        int u = (t >= off) ? sm[t - off] : 0;
        __syncthreads();
        sm[t] += u;
        __syncthreads();
    }
    g_partx[t] = sm[t] - v;  // exclusive
}

__global__ void k_scan3() {
    int i = blockIdx.x * blockDim.x + threadIdx.x;
    if (i < N_NODES) {
        int rs = g_incl[i] - g_cnt[i] + g_partx[i >> 10];
        g_row_start[i] = rs;
        g_cursor[i] = rs;
    }
    if (i == 0) g_row_start[N_NODES] = N_EDGES;
}

__global__ void k_fill(const int* __restrict__ ei) {
    int e = blockIdx.x * blockDim.x + threadIdx.x;
    if (e < N_EDGES) {
        unsigned s = (unsigned)ei[e];
        unsigned d = (unsigned)ei[N_EDGES + e];
        if (s < N_NODES && d < N_NODES) {
            int pos = atomicAdd(&g_cursor[d], 1);
            g_csr_src[pos] = s;
            g_csr_w[pos] = g_dis[s];
        }
    }
}

// ---------------- GEMM1: g0 = X @ W1 (f32x2, fp16 output) ----------------
// 64 rows/block, 256 threads. thread = 8 rows (as 4 f32x2 pairs) x 4 cols.
__global__ void __launch_bounds__(256) k_gemm1(const float* __restrict__ X,
                                               const float* __restrict__ W) {
    __shared__ float xsT[128][64];
    const int tid = threadIdx.x;
    const int row0 = blockIdx.x * 64;

    {   // load + transpose X tile [64x128] into xsT[k][r] with segment swizzle
        int row = tid >> 2, seg = tid & 3;
        int gr = row0 + row;
        int rs = row ^ (seg << 3);
        if (gr < N_NODES) {
            const float4* xr = (const float4*)(X + (size_t)gr * 128 + seg * 32);
#pragma unroll
            for (int i = 0; i < 8; i++) {
                float4 v = xr[i];
                int c = seg * 32 + i * 4;
                xsT[c + 0][rs] = v.x; xsT[c + 1][rs] = v.y;
                xsT[c + 2][rs] = v.z; xsT[c + 3][rs] = v.w;
            }
        } else {
#pragma unroll
            for (int i = 0; i < 8; i++) {
                int c = seg * 32 + i * 4;
                xsT[c + 0][rs] = 0.f; xsT[c + 1][rs] = 0.f;
                xsT[c + 2][rs] = 0.f; xsT[c + 3][rs] = 0.f;
            }
        }
    }
    __syncthreads();

    const int ty = tid >> 5, lane = tid & 31, col = lane * 4;
    unsigned long long acc[4][4];
#pragma unroll
    for (int i = 0; i < 4; i++)
#pragma unroll
        for (int j = 0; j < 4; j++) acc[i][j] = 0ULL;

    for (int q = 0; q < 4; q++) {
        const int rb = ((ty ^ q) & 7) * 8;
#pragma unroll
        for (int kk = 0; kk < 32; kk++) {
            const int k = q * 32 + kk;
            ulonglong2 xa = *(const ulonglong2*)&xsT[k][rb];      // rows +0,+1 | +2,+3
            ulonglong2 xb = *(const ulonglong2*)&xsT[k][rb + 4];  // rows +4,+5 | +6,+7
            float4 wv = *(const float4*)(W + (size_t)k * 128 + col);
            unsigned long long w0, w1, w2, w3;
            PACK_BB(w0, wv.x); PACK_BB(w1, wv.y); PACK_BB(w2, wv.z); PACK_BB(w3, wv.w);
            FMA2(acc[0][0], xa.x, w0); FMA2(acc[0][1], xa.x, w1);
            FMA2(acc[0][2], xa.x, w2); FMA2(acc[0][3], xa.x, w3);
            FMA2(acc[1][0], xa.y, w0); FMA2(acc[1][1], xa.y, w1);
            FMA2(acc[1][2], xa.y, w2); FMA2(acc[1][3], xa.y, w3);
            FMA2(acc[2][0], xb.x, w0); FMA2(acc[2][1], xb.x, w1);
            FMA2(acc[2][2], xb.x, w2); FMA2(acc[2][3], xb.x, w3);
            FMA2(acc[3][0], xb.y, w0); FMA2(acc[3][1], xb.y, w1);
            FMA2(acc[3][2], xb.y, w2); FMA2(acc[3][3], xb.y, w3);
        }
    }

#pragma unroll
    for (int rp = 0; rp < 4; rp++) {
        float lo0, hi0, lo1, hi1, lo2, hi2, lo3, hi3;
        UNPACK2(lo0, hi0, acc[rp][0]); UNPACK2(lo1, hi1, acc[rp][1]);
        UNPACK2(lo2, hi2, acc[rp][2]); UNPACK2(lo3, hi3, acc[rp][3]);
        int r0 = row0 + ty * 8 + rp * 2;
        if (r0 < N_NODES) {
            uint2 p;
            *(__half2*)&p.x = __floats2half2_rn(lo0, lo1);
            *(__half2*)&p.y = __floats2half2_rn(lo2, lo3);
            *(uint2*)(g_g0h + (size_t)r0 * 128 + col) = p;
        }
        int r1 = r0 + 1;
        if (r1 < N_NODES) {
            uint2 p;
            *(__half2*)&p.x = __floats2half2_rn(hi0, hi1);
            *(__half2*)&p.y = __floats2half2_rn(hi2, hi3);
            *(uint2*)(g_g0h + (size_t)r1 * 128 + col) = p;
        }
    }
}

// ---------------- gather aggregation (one warp per dst node, fp16 in) -------
// PASS 0: h[d]  = half( b1 + dis_d * (dis_d*g0[d] + sum_j dis[s_j]*g0[s_j]) )
// PASS 1: ah[d] = float(      dis_d * (dis_d*h[d]  + sum_j dis[s_j]*h[s_j]) )
template <int PASS>
__global__ void __launch_bounds__(256) k_gather(const float* __restrict__ b1) {
    int w = (blockIdx.x * 256 + threadIdx.x) >> 5;
    if (w >= N_NODES) return;
    int lane = threadIdx.x & 31;
    const __half* __restrict__ fin = (PASS == 0) ? g_g0h : g_hh;

    int start = g_row_start[w];
    int end   = g_row_start[w + 1];
    float disd = g_dis[w];
    const int fo = lane * 4;  // 4 features per lane

    uint2 sp = *(const uint2*)(fin + (size_t)w * 128 + fo);
    float2 s01 = __half22float2(*(__half2*)&sp.x);
    float2 s23 = __half22float2(*(__half2*)&sp.y);
    float4 acc = make_float4(s01.x * disd, s01.y * disd, s23.x * disd, s23.y * disd);

    int j = start;
    for (; j + 4 <= end; j += 4) {
        int s0 = g_csr_src[j + 0], s1 = g_csr_src[j + 1];
        int s2 = g_csr_src[j + 2], s3 = g_csr_src[j + 3];
        float w0 = g_csr_w[j + 0], w1 = g_csr_w[j + 1];
        float w2 = g_csr_w[j + 2], w3 = g_csr_w[j + 3];
        uint2 p0 = *(const uint2*)(fin + (size_t)s0 * 128 + fo);
        uint2 p1 = *(const uint2*)(fin + (size_t)s1 * 128 + fo);
        uint2 p2 = *(const uint2*)(fin + (size_t)s2 * 128 + fo);
        uint2 p3 = *(const uint2*)(fin + (size_t)s3 * 128 + fo);
        {
            float2 a = __half22float2(*(__half2*)&p0.x), b = __half22float2(*(__half2*)&p0.y);
            acc.x += a.x * w0; acc.y += a.y * w0; acc.z += b.x * w0; acc.w += b.y * w0;
        }
        {
            float2 a = __half22float2(*(__half2*)&p1.x), b = __half22float2(*(__half2*)&p1.y);
            acc.x += a.x * w1; acc.y += a.y * w1; acc.z += b.x * w1; acc.w += b.y * w1;
        }
        {
            float2 a = __half22float2(*(__half2*)&p2.x), b = __half22float2(*(__half2*)&p2.y);
            acc.x += a.x * w2; acc.y += a.y * w2; acc.z += b.x * w2; acc.w += b.y * w2;
        }
        {
            float2 a = __half22float2(*(__half2*)&p3.x), b = __half22float2(*(__half2*)&p3.y);
            acc.x += a.x * w3; acc.y += a.y * w3; acc.z += b.x * w3; acc.w += b.y * w3;
        }
    }
    for (; j < end; j++) {
        int s = g_csr_src[j];
        float ws = g_csr_w[j];
        uint2 p = *(const uint2*)(fin + (size_t)s * 128 + fo);
        float2 a = __half22float2(*(__half2*)&p.x), b = __half22float2(*(__half2*)&p.y);
        acc.x += a.x * ws; acc.y += a.y * ws; acc.z += b.x * ws; acc.w += b.y * ws;
    }

    acc.x *= disd; acc.y *= disd; acc.z *= disd; acc.w *= disd;
    if (PASS == 0) {
        float4 bv = *(const float4*)(b1 + fo);
        acc.x += bv.x; acc.y += bv.y; acc.z += bv.z; acc.w += bv.w;
        uint2 p;
        *(__half2*)&p.x = __floats2half2_rn(acc.x, acc.y);
        *(__half2*)&p.y = __floats2half2_rn(acc.z, acc.w);
        *(uint2*)(g_hh + (size_t)w * 128 + fo) = p;
    } else {
        *(float4*)(g_ah + (size_t)w * 128 + fo) = acc;
    }
}

// ---------------- GEMM2 + epilogue (f32x2) ----------------
// mu = ah@Wmu + bmu ; ls = ah@Wls + bls ; z = mu + eps*exp(ls)
__global__ void __launch_bounds__(256) k_gemm2(const float* __restrict__ Wmu,
                                               const float* __restrict__ bmu,
                                               const float* __restrict__ Wls,
                                               const float* __restrict__ bls,
                                               const float* __restrict__ eps,
                                               float* __restrict__ out) {
    __shared__ float xsT[128][64];
    const int tid = threadIdx.x;
    const int row0 = blockIdx.x * 64;

    {
        int row = tid >> 2, seg = tid & 3;
        int gr = row0 + row;
        int rs = row ^ (seg << 3);
        if (gr < N_NODES) {
            const float4* xr = (const float4*)(g_ah + (size_t)gr * 128 + seg * 32);
#pragma unroll
            for (int i = 0; i < 8; i++) {
                float4 v = xr[i];
                int c = seg * 32 + i * 4;
                xsT[c + 0][rs] = v.x; xsT[c + 1][rs] = v.y;
                xsT[c + 2][rs] = v.z; xsT[c + 3][rs] = v.w;
            }
        } else {
#pragma unroll
            for (int i = 0; i < 8; i++) {
                int c = seg * 32 + i * 4;
                xsT[c + 0][rs] = 0.f; xsT[c + 1][rs] = 0.f;
                xsT[c + 2][rs] = 0.f; xsT[c + 3][rs] = 0.f;
            }
        }
    }
    __syncthreads();

    const int ty = tid >> 5, lane = tid & 31;
    const int jc = lane * 2;  // 2 output cols per thread for each of mu/ls

    unsigned long long am[4][2], al[4][2];
#pragma unroll
    for (int i = 0; i < 4; i++) {
        am[i][0] = am[i][1] = 0ULL;
        al[i][0] = al[i][1] = 0ULL;
    }

    for (int q = 0; q < 4; q++) {
        const int rb = ((ty ^ q) & 7) * 8;
#pragma unroll
        for (int kk = 0; kk < 32; kk++) {
            const int k = q * 32 + kk;
            ulonglong2 xa = *(const ulonglong2*)&xsT[k][rb];
            ulonglong2 xb = *(const ulonglong2*)&xsT[k][rb + 4];
            float2 wm = *(const float2*)(Wmu + (size_t)k * 64 + jc);
            float2 wl = *(const float2*)(Wls + (size_t)k * 64 + jc);
            unsigned long long wm0, wm1, wl0, wl1;
            PACK_BB(wm0, wm.x); PACK_BB(wm1, wm.y);
            PACK_BB(wl0, wl.x); PACK_BB(wl1, wl.y);
            FMA2(am[0][0], xa.x, wm0); FMA2(am[0][1], xa.x, wm1);
            FMA2(am[1][0], xa.y, wm0); FMA2(am[1][1], xa.y, wm1);
            FMA2(am[2][0], xb.x, wm0); FMA2(am[2][1], xb.x, wm1);
            FMA2(am[3][0], xb.y, wm0); FMA2(am[3][1], xb.y, wm1);
            FMA2(al[0][0], xa.x, wl0); FMA2(al[0][1], xa.x, wl1);
            FMA2(al[1][0], xa.y, wl0); FMA2(al[1][1], xa.y, wl1);
            FMA2(al[2][0], xb.x, wl0); FMA2(al[2][1], xb.x, wl1);
            FMA2(al[3][0], xb.y, wl0); FMA2(al[3][1], xb.y, wl1);
        }
    }

    const size_t NOUT = (size_t)N_NODES * C_OUT;
    float bm0 = bmu[jc], bm1 = bmu[jc + 1];
    float bl0 = bls[jc], bl1 = bls[jc + 1];
#pragma unroll
    for (int rp = 0; rp < 4; rp++) {
        float m0lo, m0hi, m1lo, m1hi, l0lo, l0hi, l1lo, l1hi;
        UNPACK2(m0lo, m0hi, am[rp][0]); UNPACK2(m1lo, m1hi, am[rp][1]);
        UNPACK2(l0lo, l0hi, al[rp][0]); UNPACK2(l1lo, l1hi, al[rp][1]);
#pragma unroll
        for (int half = 0; half < 2; half++) {
            int r = row0 + ty * 8 + rp * 2 + half;
            if (r >= N_NODES) continue;
            float mu0 = (half ? m0hi : m0lo) + bm0;
            float mu1 = (half ? m1hi : m1lo) + bm1;
            float ls0 = (half ? l0hi : l0lo) + bl0;
            float ls1 = (half ? l1hi : l1lo) + bl1;
            float2 ev = *(const float2*)(eps + (size_t)r * 64 + jc);
            float z0 = mu0 + ev.x * __expf(ls0);
            float z1 = mu1 + ev.y * __expf(ls1);
            size_t off = (size_t)r * 64 + jc;
            *(float2*)(out + off)            = make_float2(z0, z1);
            *(float2*)(out + NOUT + off)     = make_float2(mu0, mu1);
            *(float2*)(out + 2 * NOUT + off) = make_float2(ls0, ls1);
        }
    }
}

extern "C" void kernel_launch(void* const* d_in, const int* in_sizes, int n_in,
                              void* d_out, int out_size) {
    const float* x   = (const float*)d_in[0];
    const int*   ei  = (const int*)d_in[1];   // int32 (JAX demotes int64)
    const float* W1  = (const float*)d_in[2];
    const float* b1  = (const float*)d_in[3];
    const float* Wmu = (const float*)d_in[4];
    const float* bmu = (const float*)d_in[5];
    const float* Wls = (const float*)d_in[6];
    const float* bls = (const float*)d_in[7];
    const float* eps = (const float*)d_in[8];
    float* out       = (float*)d_out;
    (void)in_sizes; (void)n_in; (void)out_size;

    // degree + CSR build
    k_zero_cnt<<<(N_NODES + 255) / 256, 256>>>();
    k_hist<<<(N_EDGES + 255) / 256, 256>>>(ei);
    k_dis<<<(N_NODES + 255) / 256, 256>>>();
    k_scan1<<<NB_SCAN, 1024>>>();
    k_scan2<<<1, 128>>>();
    k_scan3<<<(N_NODES + 255) / 256, 256>>>();
    k_fill<<<(N_EDGES + 255) / 256, 256>>>(ei);

    // g0 = x @ W1  (fp16 out)
    k_gemm1<<<(N_NODES + 63) / 64, 256>>>(x, W1);
    // h = Agg(g0) + b1  (fp16 out)
    k_gather<0><<<(N_NODES + 7) / 8, 256>>>(b1);
    // ah = Agg(h)  (fp32 out)
    k_gather<1><<<(N_NODES + 7) / 8, 256>>>(b1);
    // mu/logstd/z
    k_gemm2<<<(N_NODES + 63) / 64, 256>>>(Wmu, bmu, Wls, bls, eps, out);
}